// round 4
// baseline (speedup 1.0000x reference)
#include <cuda_runtime.h>
#include <cuda_bf16.h>
#include <mma.h>
#include <math.h>
#include <stdint.h>

using namespace nvcuda;
typedef __nv_bfloat16 bf16;

#define TOK     16384
#define DMODEL  1024
#define HID     4096
#define NSEQ    256
#define DKH     128
#define QKVN    3072

// ---------------- scratch ----------------
__device__ bf16  g_xn    [2L*TOK*DMODEL];
__device__ bf16  g_qkv   [2L*TOK*QKVN];      // [stream][tok][3072] (Q|K|V)
__device__ bf16  g_attn  [2L*TOK*DMODEL];
__device__ float g_attres[2L*TOK*DMODEL];
__device__ bf16  g_h1    [2L*TOK*HID];
__device__ bf16  g_wqkv  [2L*QKVN*DMODEL];   // transposed [N,K]
__device__ bf16  g_wo    [2L*DMODEL*DMODEL];
__device__ bf16  g_w1    [2L*HID*DMODEL];
__device__ bf16  g_w2    [2L*DMODEL*HID];

// ---------------- helpers ----------------
__device__ __forceinline__ void cp_async16(void* d, const void* s) {
    unsigned ds = (unsigned)__cvta_generic_to_shared(d);
    asm volatile("cp.async.cg.shared.global [%0], [%1], 16;\n" :: "r"(ds), "l"(s));
}
__device__ __forceinline__ void cp_commit() { asm volatile("cp.async.commit_group;\n"); }

// ---------------- transpose + fp32->bf16 convert: src[K,N] -> dst[N,K] ----------------
__global__ void cvtT_kernel(const float* __restrict__ src, bf16* __restrict__ dst, int K, int N) {
    __shared__ float t[32][33];
    int n0 = blockIdx.x * 32, k0 = blockIdx.y * 32;
    int tx = threadIdx.x & 31, ty = threadIdx.x >> 5;
#pragma unroll
    for (int i = 0; i < 32; i += 8)
        t[ty + i][tx] = src[(long)(k0 + ty + i) * N + n0 + tx];
    __syncthreads();
#pragma unroll
    for (int i = 0; i < 32; i += 8)
        dst[(long)(n0 + ty + i) * K + k0 + tx] = __float2bfloat16(t[tx][ty + i]);
}

// ---------------- LayerNorm (fp32 in -> bf16 out) ----------------
__global__ void ln_kernel(const float* __restrict__ x, const float* __restrict__ gamma,
                          const float* __restrict__ beta, bf16* __restrict__ out) {
    int warp = threadIdx.x >> 5, lane = threadIdx.x & 31;
    long row = (long)blockIdx.x * 8 + warp;
    const float* xr = x + row * DMODEL;
    float4 v[8];
    float s = 0.f, s2 = 0.f;
#pragma unroll
    for (int i = 0; i < 8; i++) {
        v[i] = *reinterpret_cast<const float4*>(xr + i * 128 + lane * 4);
        s  += v[i].x + v[i].y + v[i].z + v[i].w;
        s2 += v[i].x*v[i].x + v[i].y*v[i].y + v[i].z*v[i].z + v[i].w*v[i].w;
    }
#pragma unroll
    for (int o = 16; o > 0; o >>= 1) {
        s  += __shfl_xor_sync(0xffffffffu, s,  o);
        s2 += __shfl_xor_sync(0xffffffffu, s2, o);
    }
    float m  = s * (1.f / 1024.f);
    float var = s2 * (1.f / 1024.f) - m * m;
    float rs = rsqrtf(var + 1e-5f);
    bf16* orow = out + row * DMODEL;
#pragma unroll
    for (int i = 0; i < 8; i++) {
        int c = i * 128 + lane * 4;
        float4 g4 = *reinterpret_cast<const float4*>(gamma + c);
        float4 b4 = *reinterpret_cast<const float4*>(beta + c);
        float o0 = (v[i].x - m) * rs * g4.x + b4.x;
        float o1 = (v[i].y - m) * rs * g4.y + b4.y;
        float o2 = (v[i].z - m) * rs * g4.z + b4.z;
        float o3 = (v[i].w - m) * rs * g4.w + b4.w;
        __nv_bfloat162 p0 = __floats2bfloat162_rn(o0, o1);
        __nv_bfloat162 p1 = __floats2bfloat162_rn(o2, o3);
        uint2 p;
        p.x = *reinterpret_cast<unsigned*>(&p0);
        p.y = *reinterpret_cast<unsigned*>(&p1);
        *reinterpret_cast<uint2*>(orow + c) = p;
    }
}

// ---------------- wmma GEMM: C[M,Nfull] = A[M,K] @ Bt[N,K]^T + epilogue ----------------
// CTA tile 128x256xBK32, 8 warps of 64x64, 4-stage cp.async pipeline.
// EPI 0: bf16 out = acc + bias
// EPI 1: bf16 out = gelu_exact(acc + bias)
// EPI 2: f32  out = c[ci_res]*res + c[ci_out]*(acc + bias)
#define PIPE  4
#define LDA   40
#define LDB   40
#define ASZ   (128 * LDA * 2)        // 10240 B
#define BSZ   (256 * LDB * 2)        // 20480 B
#define STG   (ASZ + BSZ)            // 30720 B
#define GSMEM (PIPE * STG)           // 122880 B

template <int EPI>
__global__ void __launch_bounds__(256, 1) tgemm_kernel(
    const bf16* __restrict__ A, const bf16* __restrict__ Bt,
    const float* __restrict__ bias, const float* __restrict__ res,
    const float* __restrict__ coeffs, int ci_res, int ci_out,
    void* __restrict__ Cout, int Nfull, int K)
{
    extern __shared__ char sm[];
    int tid = threadIdx.x, wid = tid >> 5, lane = tid & 31;
    int warpM = wid & 1, warpN = wid >> 1;
    long bm = (long)blockIdx.y * 128;
    long bn = (long)blockIdx.x * 256;
    int KT = K >> 5;

    wmma::fragment<wmma::accumulator, 16, 16, 16, float> acc[4][4];
#pragma unroll
    for (int i = 0; i < 4; i++)
#pragma unroll
        for (int j = 0; j < 4; j++) wmma::fill_fragment(acc[i][j], 0.f);

    int r4 = tid >> 2;
    int c8 = (tid & 3) * 8;

    // prefetch PIPE-1 stages
#pragma unroll
    for (int s = 0; s < PIPE - 1; s++) {
        bf16* As = (bf16*)(sm + s * STG);
        bf16* Bs = (bf16*)(sm + s * STG + ASZ);
        long koff = (long)s * 32;
#pragma unroll
        for (int j = 0; j < 2; j++) {
            int r = r4 + j * 64;
            cp_async16(&As[r * LDA + c8], A + (bm + r) * K + koff + c8);
        }
#pragma unroll
        for (int j = 0; j < 4; j++) {
            int r = r4 + j * 64;
            cp_async16(&Bs[r * LDB + c8], Bt + (bn + r) * K + koff + c8);
        }
        cp_commit();
    }

    for (int kt = 0; kt < KT; kt++) {
        int pf = kt + PIPE - 1;
        if (pf < KT) {
            int ps = pf % PIPE;
            bf16* As = (bf16*)(sm + ps * STG);
            bf16* Bs = (bf16*)(sm + ps * STG + ASZ);
            long koff = (long)pf * 32;
#pragma unroll
            for (int j = 0; j < 2; j++) {
                int r = r4 + j * 64;
                cp_async16(&As[r * LDA + c8], A + (bm + r) * K + koff + c8);
            }
#pragma unroll
            for (int j = 0; j < 4; j++) {
                int r = r4 + j * 64;
                cp_async16(&Bs[r * LDB + c8], Bt + (bn + r) * K + koff + c8);
            }
        }
        cp_commit();
        asm volatile("cp.async.wait_group 3;\n");
        __syncthreads();

        int st = kt % PIPE;
        bf16* As = (bf16*)(sm + st * STG);
        bf16* Bs = (bf16*)(sm + st * STG + ASZ);
#pragma unroll
        for (int ks = 0; ks < 2; ks++) {
            wmma::fragment<wmma::matrix_a, 16, 16, 16, bf16, wmma::row_major> a[4];
            wmma::fragment<wmma::matrix_b, 16, 16, 16, bf16, wmma::col_major> b[4];
#pragma unroll
            for (int i = 0; i < 4; i++)
                wmma::load_matrix_sync(a[i], &As[(warpM * 64 + i * 16) * LDA + ks * 16], LDA);
#pragma unroll
            for (int j = 0; j < 4; j++)
                wmma::load_matrix_sync(b[j], &Bs[(warpN * 64 + j * 16) * LDB + ks * 16], LDB);
#pragma unroll
            for (int i = 0; i < 4; i++)
#pragma unroll
                for (int j = 0; j < 4; j++)
                    wmma::mma_sync(acc[i][j], a[i], b[j], acc[i][j]);
        }
        __syncthreads();
    }

    // ---- epilogue: per-warp smem staging ----
    float* ebuf = (float*)(sm) + wid * 256;
    float cr = 0.f, co = 0.f;
    if (EPI == 2) { cr = coeffs[ci_res]; co = coeffs[ci_out]; }
#pragma unroll
    for (int i = 0; i < 4; i++) {
#pragma unroll
        for (int j = 0; j < 4; j++) {
            wmma::store_matrix_sync(ebuf, acc[i][j], 16, wmma::mem_row_major);
            __syncwarp();
            long r0 = bm + warpM * 64 + i * 16;
            long c0 = bn + warpN * 64 + j * 16;
#pragma unroll
            for (int e = 0; e < 8; e++) {
                int idx = lane + e * 32;
                int rr = idx >> 4, cc = idx & 15;
                long gr = r0 + rr, gc = c0 + cc;
                float val = ebuf[idx] + bias[gc];
                if (EPI == 0) {
                    ((bf16*)Cout)[gr * Nfull + gc] = __float2bfloat16(val);
                } else if (EPI == 1) {
                    float gel = 0.5f * val * (1.f + erff(val * 0.70710678118654752f));
                    ((bf16*)Cout)[gr * Nfull + gc] = __float2bfloat16(gel);
                } else {
                    ((float*)Cout)[gr * Nfull + gc] =
                        cr * res[gr * Nfull + gc] + co * val;
                }
            }
            __syncwarp();
        }
    }
}

// ---------------- fused cross-attention (wmma), QKV stride 3072 ----------------
#define SMEM_ATT 197632

__global__ void __launch_bounds__(256) attn_kernel() {
    extern __shared__ char smraw[];
    bf16*  Ks = (bf16*)smraw;
    bf16*  Vs = Ks + 256 * 136;
    bf16*  Qs = Vs + 256 * 136;
    float* Ss = (float*)(Qs + 32 * 136);
    bf16*  Ps = (bf16*)(Ss + 32 * 256);
    float* Os = Ss;

    int tid = threadIdx.x, wid = tid >> 5, lane = tid & 31;
    int bx = blockIdx.x;
    int s  = bx >> 9;
    int bh = bx & 511;
    int b = bh >> 3, h = bh & 7;

    const bf16* qs_op = g_qkv + (long)(1 - s) * TOK * QKVN;
    const bf16* qs_s  = g_qkv + (long)s * TOK * QKVN;
    const bf16* Qg = qs_op + ((long)b * NSEQ) * QKVN + 0 * DMODEL + h * DKH;
    const bf16* Kg = qs_s  + ((long)b * NSEQ) * QKVN + 1 * DMODEL + h * DKH;
    const bf16* Vg = qs_s  + ((long)b * NSEQ) * QKVN + 2 * DMODEL + h * DKH;
    bf16*       Og = g_attn + (long)s * TOK * DMODEL + ((long)b * NSEQ) * DMODEL + h * DKH;

#pragma unroll
    for (int i = 0; i < 16; i++) {
        int v = tid + i * 256;
        int r = v >> 4, c8 = (v & 15) * 8;
        *(uint4*)&Ks[r * 136 + c8] = *(const uint4*)&Kg[(long)r * QKVN + c8];
        *(uint4*)&Vs[r * 136 + c8] = *(const uint4*)&Vg[(long)r * QKVN + c8];
    }
    __syncthreads();

    const float scale = 0.08838834764831845f;

    for (int qc = 0; qc < 8; qc++) {
#pragma unroll
        for (int i = 0; i < 2; i++) {
            int v = tid + i * 256;
            int r = v >> 4, c8 = (v & 15) * 8;
            *(uint4*)&Qs[r * 136 + c8] = *(const uint4*)&Qg[(long)(qc * 32 + r) * QKVN + c8];
        }
        __syncthreads();

        {
            wmma::fragment<wmma::accumulator, 16, 16, 16, float> c[2][2];
#pragma unroll
            for (int i = 0; i < 2; i++)
#pragma unroll
                for (int j = 0; j < 2; j++) wmma::fill_fragment(c[i][j], 0.f);
#pragma unroll
            for (int kt = 0; kt < 8; kt++) {
                wmma::fragment<wmma::matrix_a, 16, 16, 16, bf16, wmma::row_major> a[2];
                wmma::fragment<wmma::matrix_b, 16, 16, 16, bf16, wmma::col_major> bb[2];
#pragma unroll
                for (int i = 0; i < 2; i++)
                    wmma::load_matrix_sync(a[i], &Qs[(i * 16) * 136 + kt * 16], 136);
#pragma unroll
                for (int j = 0; j < 2; j++)
                    wmma::load_matrix_sync(bb[j], &Ks[(wid * 32 + j * 16) * 136 + kt * 16], 136);
#pragma unroll
                for (int i = 0; i < 2; i++)
#pragma unroll
                    for (int j = 0; j < 2; j++)
                        wmma::mma_sync(c[i][j], a[i], bb[j], c[i][j]);
            }
#pragma unroll
            for (int i = 0; i < 2; i++)
#pragma unroll
                for (int j = 0; j < 2; j++) {
#pragma unroll
                    for (int t = 0; t < c[i][j].num_elements; t++) c[i][j].x[t] *= scale;
                    wmma::store_matrix_sync(&Ss[(i * 16) * 256 + wid * 32 + j * 16],
                                            c[i][j], 256, wmma::mem_row_major);
                }
        }
        __syncthreads();

        {
#pragma unroll
            for (int rq = 0; rq < 4; rq++) {
                int row = wid * 4 + rq;
                float* srow = Ss + row * 256;
                float vals[8];
                float mx = -1e30f;
#pragma unroll
                for (int i = 0; i < 8; i++) { vals[i] = srow[lane + i * 32]; mx = fmaxf(mx, vals[i]); }
#pragma unroll
                for (int o = 16; o > 0; o >>= 1) mx = fmaxf(mx, __shfl_xor_sync(0xffffffffu, mx, o));
                float sum = 0.f;
#pragma unroll
                for (int i = 0; i < 8; i++) { vals[i] = __expf(vals[i] - mx); sum += vals[i]; }
#pragma unroll
                for (int o = 16; o > 0; o >>= 1) sum += __shfl_xor_sync(0xffffffffu, sum, o);
                float inv = 1.f / sum;
#pragma unroll
                for (int i = 0; i < 8; i++)
                    Ps[row * 264 + lane + i * 32] = __float2bfloat16(vals[i] * inv);
            }
        }
        __syncthreads();

        {
            wmma::fragment<wmma::accumulator, 16, 16, 16, float> c2[2];
#pragma unroll
            for (int i = 0; i < 2; i++) wmma::fill_fragment(c2[i], 0.f);
#pragma unroll
            for (int kt = 0; kt < 16; kt++) {
                wmma::fragment<wmma::matrix_a, 16, 16, 16, bf16, wmma::row_major> a[2];
                wmma::fragment<wmma::matrix_b, 16, 16, 16, bf16, wmma::row_major> bb;
#pragma unroll
                for (int i = 0; i < 2; i++)
                    wmma::load_matrix_sync(a[i], &Ps[(i * 16) * 264 + kt * 16], 264);
                wmma::load_matrix_sync(bb, &Vs[(kt * 16) * 136 + wid * 16], 136);
#pragma unroll
                for (int i = 0; i < 2; i++) wmma::mma_sync(c2[i], a[i], bb, c2[i]);
            }
#pragma unroll
            for (int i = 0; i < 2; i++)
                wmma::store_matrix_sync(&Os[(i * 16) * 128 + wid * 16], c2[i], 128, wmma::mem_row_major);
        }
        __syncthreads();

#pragma unroll
        for (int i = 0; i < 16; i++) {
            int e = tid + i * 256;
            int r = e >> 7, cc = e & 127;
            Og[(long)(qc * 32 + r) * DMODEL + cc] = __float2bfloat16(Os[r * 128 + cc]);
        }
        __syncthreads();
    }
}

// ---------------- host ----------------
extern "C" void kernel_launch(void* const* d_in, const int* in_sizes, int n_in,
                              void* d_out, int out_size) {
    const float* rgb   = (const float*)d_in[0];
    const float* ir    = (const float*)d_in[1];
    const float* ln1g  = (const float*)d_in[2];
    const float* ln1b  = (const float*)d_in[3];
    const float* ln2g  = (const float*)d_in[4];
    const float* ln2b  = (const float*)d_in[5];
    const float* Wqv   = (const float*)d_in[6];
    const float* bqv   = (const float*)d_in[7];
    const float* Wqi   = (const float*)d_in[8];
    const float* bqi   = (const float*)d_in[9];
    const float* Wov   = (const float*)d_in[10];
    const float* bov   = (const float*)d_in[11];
    const float* Woi   = (const float*)d_in[12];
    const float* boi   = (const float*)d_in[13];
    const float* blkg  = (const float*)d_in[14];
    const float* blkb  = (const float*)d_in[15];
    const float* W1v   = (const float*)d_in[16];
    const float* b1v   = (const float*)d_in[17];
    const float* W2v   = (const float*)d_in[18];
    const float* b2v   = (const float*)d_in[19];
    const float* W1i   = (const float*)d_in[20];
    const float* b1i   = (const float*)d_in[21];
    const float* W2i   = (const float*)d_in[22];
    const float* b2i   = (const float*)d_in[23];
    const float* coeffs = (const float*)d_in[24];

    bf16 *xn, *qkv, *attn, *h1, *wqkv, *wo, *w1, *w2;
    float* attres;
    cudaGetSymbolAddress((void**)&xn, g_xn);
    cudaGetSymbolAddress((void**)&qkv, g_qkv);
    cudaGetSymbolAddress((void**)&attn, g_attn);
    cudaGetSymbolAddress((void**)&attres, g_attres);
    cudaGetSymbolAddress((void**)&h1, g_h1);
    cudaGetSymbolAddress((void**)&wqkv, g_wqkv);
    cudaGetSymbolAddress((void**)&wo, g_wo);
    cudaGetSymbolAddress((void**)&w1, g_w1);
    cudaGetSymbolAddress((void**)&w2, g_w2);

    const long DD = (long)DMODEL * DMODEL;
    const long TD = (long)TOK * DMODEL;
    const long QD = (long)TOK * QKVN;

    // transpose-convert weights to [N, K] bf16
    for (int t = 0; t < 3; t++) {
        cvtT_kernel<<<dim3(DMODEL/32, DMODEL/32), 256>>>(Wqv + t * DD, wqkv + t * DD, DMODEL, DMODEL);
        cvtT_kernel<<<dim3(DMODEL/32, DMODEL/32), 256>>>(Wqi + t * DD, wqkv + 3 * DD + t * DD, DMODEL, DMODEL);
    }
    cvtT_kernel<<<dim3(DMODEL/32, DMODEL/32), 256>>>(Wov, wo, DMODEL, DMODEL);
    cvtT_kernel<<<dim3(DMODEL/32, DMODEL/32), 256>>>(Woi, wo + DD, DMODEL, DMODEL);
    cvtT_kernel<<<dim3(HID/32, DMODEL/32), 256>>>(W1v, w1, DMODEL, HID);
    cvtT_kernel<<<dim3(HID/32, DMODEL/32), 256>>>(W1i, w1 + (long)HID * DMODEL, DMODEL, HID);
    cvtT_kernel<<<dim3(DMODEL/32, HID/32), 256>>>(W2v, w2, HID, DMODEL);
    cvtT_kernel<<<dim3(DMODEL/32, HID/32), 256>>>(W2i, w2 + (long)DMODEL * HID, HID, DMODEL);

    // LN per stream
    ln_kernel<<<TOK / 8, 256>>>(rgb, ln1g, ln1b, xn);
    ln_kernel<<<TOK / 8, 256>>>(ir, ln2g, ln2b, xn + TD);

    cudaFuncSetAttribute(tgemm_kernel<0>, cudaFuncAttributeMaxDynamicSharedMemorySize, GSMEM);
    cudaFuncSetAttribute(tgemm_kernel<1>, cudaFuncAttributeMaxDynamicSharedMemorySize, GSMEM);
    cudaFuncSetAttribute(tgemm_kernel<2>, cudaFuncAttributeMaxDynamicSharedMemorySize, GSMEM);

    // fused QKV: [16384,1024] @ [3072,1024]^T
    for (int s = 0; s < 2; s++) {
        tgemm_kernel<0><<<dim3(QKVN/256, TOK/128), 256, GSMEM>>>(
            xn + s * TD, wqkv + (long)s * 3 * DD, s ? bqi : bqv,
            nullptr, nullptr, 0, 0, qkv + s * QD, QKVN, DMODEL);
    }

    // fused cross attention
    cudaFuncSetAttribute(attn_kernel, cudaFuncAttributeMaxDynamicSharedMemorySize, SMEM_ATT);
    attn_kernel<<<1024, 256, SMEM_ATT>>>();

    // output projection + coeff residual -> fp32 attres
    for (int s = 0; s < 2; s++) {
        tgemm_kernel<2><<<dim3(DMODEL/256, TOK/128), 256, GSMEM>>>(
            attn + s * TD, wo + s * DD, s ? boi : bov,
            s ? ir : rgb, coeffs, 2 * s, 2 * s + 1,
            attres + s * TD, DMODEL, DMODEL);
    }

    // block LN (shared params)
    ln_kernel<<<TOK / 8, 256>>>(attres, blkg, blkb, xn);
    ln_kernel<<<TOK / 8, 256>>>(attres + TD, blkg, blkb, xn + TD);

    // MLP1 (gelu)
    for (int s = 0; s < 2; s++) {
        tgemm_kernel<1><<<dim3(HID/256, TOK/128), 256, GSMEM>>>(
            xn + s * TD, w1 + (long)s * HID * DMODEL, s ? b1i : b1v,
            nullptr, nullptr, 0, 0, h1 + (long)s * TOK * HID, HID, DMODEL);
    }

    // MLP2 + coeff residual -> d_out (fp32)
    for (int s = 0; s < 2; s++) {
        tgemm_kernel<2><<<dim3(DMODEL/256, TOK/128), 256, GSMEM>>>(
            h1 + (long)s * TOK * HID, w2 + (long)s * DMODEL * HID, s ? b2i : b2v,
            attres + s * TD, coeffs, 4 + 2 * s, 5 + 2 * s,
            (float*)d_out + s * TD, DMODEL, HID);
    }
}

// round 8
// speedup vs baseline: 2.0674x; 2.0674x over previous
#include <cuda_runtime.h>
#include <cuda_bf16.h>
#include <mma.h>
#include <math.h>
#include <stdint.h>

using namespace nvcuda;
typedef __nv_bfloat16 bf16;

#define TOK     16384
#define DMODEL  1024
#define HID     4096
#define NSEQ    256
#define DKH     128
#define QKVN    3072

// ---------------- scratch ----------------
__device__ bf16  g_xn    [2L*TOK*DMODEL];
__device__ bf16  g_qkv   [2L*TOK*QKVN];      // [stream][tok][3072] (Q|K|V)
__device__ bf16  g_attn  [2L*TOK*DMODEL];
__device__ float g_attres[2L*TOK*DMODEL];
__device__ bf16  g_h1    [2L*TOK*HID];
__device__ bf16  g_wqkv  [2L*QKVN*DMODEL];   // transposed [N,K]
__device__ bf16  g_wo    [2L*DMODEL*DMODEL];
__device__ bf16  g_w1    [2L*HID*DMODEL];
__device__ bf16  g_w2    [2L*DMODEL*HID];

// ---------------- helpers ----------------
__device__ __forceinline__ void cp_async16(void* d, const void* s) {
    unsigned ds = (unsigned)__cvta_generic_to_shared(d);
    asm volatile("cp.async.cg.shared.global [%0], [%1], 16;\n" :: "r"(ds), "l"(s));
}
__device__ __forceinline__ void cp_commit() { asm volatile("cp.async.commit_group;\n"); }

// ---------------- transpose + fp32->bf16 convert: src[K,N] -> dst[N,K] ----------------
__global__ void cvtT_kernel(const float* __restrict__ src, bf16* __restrict__ dst, int K, int N) {
    __shared__ float t[32][33];
    int n0 = blockIdx.x * 32, k0 = blockIdx.y * 32;
    int tx = threadIdx.x & 31, ty = threadIdx.x >> 5;
#pragma unroll
    for (int i = 0; i < 32; i += 8)
        t[ty + i][tx] = src[(long)(k0 + ty + i) * N + n0 + tx];
    __syncthreads();
#pragma unroll
    for (int i = 0; i < 32; i += 8)
        dst[(long)(n0 + ty + i) * K + k0 + tx] = __float2bfloat16(t[tx][ty + i]);
}

// ---------------- LayerNorm (fp32 in -> bf16 out) ----------------
__global__ void ln_kernel(const float* __restrict__ x, const float* __restrict__ gamma,
                          const float* __restrict__ beta, bf16* __restrict__ out) {
    int warp = threadIdx.x >> 5, lane = threadIdx.x & 31;
    long row = (long)blockIdx.x * 8 + warp;
    const float* xr = x + row * DMODEL;
    float4 v[8];
    float s = 0.f, s2 = 0.f;
#pragma unroll
    for (int i = 0; i < 8; i++) {
        v[i] = *reinterpret_cast<const float4*>(xr + i * 128 + lane * 4);
        s  += v[i].x + v[i].y + v[i].z + v[i].w;
        s2 += v[i].x*v[i].x + v[i].y*v[i].y + v[i].z*v[i].z + v[i].w*v[i].w;
    }
#pragma unroll
    for (int o = 16; o > 0; o >>= 1) {
        s  += __shfl_xor_sync(0xffffffffu, s,  o);
        s2 += __shfl_xor_sync(0xffffffffu, s2, o);
    }
    float m  = s * (1.f / 1024.f);
    float var = s2 * (1.f / 1024.f) - m * m;
    float rs = rsqrtf(var + 1e-5f);
    bf16* orow = out + row * DMODEL;
#pragma unroll
    for (int i = 0; i < 8; i++) {
        int c = i * 128 + lane * 4;
        float4 g4 = *reinterpret_cast<const float4*>(gamma + c);
        float4 b4 = *reinterpret_cast<const float4*>(beta + c);
        float o0 = (v[i].x - m) * rs * g4.x + b4.x;
        float o1 = (v[i].y - m) * rs * g4.y + b4.y;
        float o2 = (v[i].z - m) * rs * g4.z + b4.z;
        float o3 = (v[i].w - m) * rs * g4.w + b4.w;
        __nv_bfloat162 p0 = __floats2bfloat162_rn(o0, o1);
        __nv_bfloat162 p1 = __floats2bfloat162_rn(o2, o3);
        uint2 p;
        p.x = *reinterpret_cast<unsigned*>(&p0);
        p.y = *reinterpret_cast<unsigned*>(&p1);
        *reinterpret_cast<uint2*>(orow + c) = p;
    }
}

// ---------------- wmma GEMM: C[M,Nfull] = A[M,K] @ Bt[N,K]^T + epilogue ----------------
// CTA 128x128, 4 warps of 64x64, BK=32, 4-stage cp.async, ONE barrier per iter, occ 2.
#define PIPE   4
#define LDT    40
#define ASTGB  (128 * LDT * 2)        // 10240 B
#define STGB   (2 * ASTGB)            // 20480 B per stage (A+B)
#define EOFF   (PIPE * STGB)          // 81920
#define GSMEM  (EOFF + 4 * 1024)      // + 4 warps * 256 floats

template <int EPI>
__global__ void __launch_bounds__(128, 2) tgemm_kernel(
    const bf16* __restrict__ A, const bf16* __restrict__ Bt,
    const float* __restrict__ bias, const float* __restrict__ res,
    const float* __restrict__ coeffs, int ci_res, int ci_out,
    void* __restrict__ Cout, int Nfull, int K)
{
    extern __shared__ char sm[];
    int tid = threadIdx.x, wid = tid >> 5, lane = tid & 31;
    int warpM = wid & 1, warpN = wid >> 1;
    long bm = (long)blockIdx.y * 128;
    long bn = (long)blockIdx.x * 128;
    int KT = K >> 5;

    wmma::fragment<wmma::accumulator, 16, 16, 16, float> acc[4][4];
#pragma unroll
    for (int i = 0; i < 4; i++)
#pragma unroll
        for (int j = 0; j < 4; j++) wmma::fill_fragment(acc[i][j], 0.f);

    // loader mapping: 512 chunks of 16B per operand, 128 threads -> 4 each
#pragma unroll
    for (int s = 0; s < PIPE - 1; s++) {
        char* stg = sm + s * STGB;
        long koff = (long)s * 32;
#pragma unroll
        for (int i = 0; i < 4; i++) {
            int id = tid + i * 128;
            int r = id >> 2, c8 = (id & 3) * 8;
            cp_async16(stg + (r * LDT + c8) * 2, A + (bm + r) * K + koff + c8);
            cp_async16(stg + ASTGB + (r * LDT + c8) * 2, Bt + (bn + r) * K + koff + c8);
        }
        cp_commit();
    }

    for (int kt = 0; kt < KT; kt++) {
        asm volatile("cp.async.wait_group 2;\n");
        __syncthreads();

        // prefetch stage kt+3 (safe: its buffer was last read in iter kt-1, barrier passed)
        int pf = kt + PIPE - 1;
        if (pf < KT) {
            char* stg = sm + (pf % PIPE) * STGB;
            long koff = (long)pf * 32;
#pragma unroll
            for (int i = 0; i < 4; i++) {
                int id = tid + i * 128;
                int r = id >> 2, c8 = (id & 3) * 8;
                cp_async16(stg + (r * LDT + c8) * 2, A + (bm + r) * K + koff + c8);
                cp_async16(stg + ASTGB + (r * LDT + c8) * 2, Bt + (bn + r) * K + koff + c8);
            }
        }
        cp_commit();

        bf16* As = (bf16*)(sm + (kt % PIPE) * STGB);
        bf16* Bs = (bf16*)(sm + (kt % PIPE) * STGB + ASTGB);
#pragma unroll
        for (int ks = 0; ks < 2; ks++) {
            wmma::fragment<wmma::matrix_a, 16, 16, 16, bf16, wmma::row_major> a[4];
            wmma::fragment<wmma::matrix_b, 16, 16, 16, bf16, wmma::col_major> b[4];
#pragma unroll
            for (int i = 0; i < 4; i++)
                wmma::load_matrix_sync(a[i], &As[(warpM * 64 + i * 16) * LDT + ks * 16], LDT);
#pragma unroll
            for (int j = 0; j < 4; j++)
                wmma::load_matrix_sync(b[j], &Bs[(warpN * 64 + j * 16) * LDT + ks * 16], LDT);
#pragma unroll
            for (int i = 0; i < 4; i++)
#pragma unroll
                for (int j = 0; j < 4; j++)
                    wmma::mma_sync(acc[i][j], a[i], b[j], acc[i][j]);
        }
    }

    // ---- epilogue (per-warp private smem staging, vectorized stores) ----
    float* ebuf = (float*)(sm + EOFF + wid * 1024);
    float cr = 0.f, co = 0.f;
    if (EPI == 2) { cr = coeffs[ci_res]; co = coeffs[ci_out]; }
    int rr = lane >> 1, half = lane & 1;
#pragma unroll
    for (int i = 0; i < 4; i++) {
#pragma unroll
        for (int j = 0; j < 4; j++) {
            wmma::store_matrix_sync(ebuf, acc[i][j], 16, wmma::mem_row_major);
            __syncwarp();
            long gr  = bm + warpM * 64 + i * 16 + rr;
            long gc0 = bn + warpN * 64 + j * 16 + half * 8;
            float4 v0 = *(float4*)&ebuf[rr * 16 + half * 8];
            float4 v1 = *(float4*)&ebuf[rr * 16 + half * 8 + 4];
            float4 b0 = *(const float4*)&bias[gc0];
            float4 b1 = *(const float4*)&bias[gc0 + 4];
            float o0 = v0.x + b0.x, o1 = v0.y + b0.y, o2 = v0.z + b0.z, o3 = v0.w + b0.w;
            float o4 = v1.x + b1.x, o5 = v1.y + b1.y, o6 = v1.z + b1.z, o7 = v1.w + b1.w;
            if (EPI == 1) {
                o0 = 0.5f*o0*(1.f+erff(o0*0.70710678f)); o1 = 0.5f*o1*(1.f+erff(o1*0.70710678f));
                o2 = 0.5f*o2*(1.f+erff(o2*0.70710678f)); o3 = 0.5f*o3*(1.f+erff(o3*0.70710678f));
                o4 = 0.5f*o4*(1.f+erff(o4*0.70710678f)); o5 = 0.5f*o5*(1.f+erff(o5*0.70710678f));
                o6 = 0.5f*o6*(1.f+erff(o6*0.70710678f)); o7 = 0.5f*o7*(1.f+erff(o7*0.70710678f));
            }
            if (EPI == 2) {
                float4 r0 = *(const float4*)&res[gr * Nfull + gc0];
                float4 r1 = *(const float4*)&res[gr * Nfull + gc0 + 4];
                float4 w0 = make_float4(cr*r0.x + co*o0, cr*r0.y + co*o1,
                                        cr*r0.z + co*o2, cr*r0.w + co*o3);
                float4 w1 = make_float4(cr*r1.x + co*o4, cr*r1.y + co*o5,
                                        cr*r1.z + co*o6, cr*r1.w + co*o7);
                *(float4*)&((float*)Cout)[gr * Nfull + gc0]     = w0;
                *(float4*)&((float*)Cout)[gr * Nfull + gc0 + 4] = w1;
            } else {
                __nv_bfloat162 p0 = __floats2bfloat162_rn(o0, o1);
                __nv_bfloat162 p1 = __floats2bfloat162_rn(o2, o3);
                __nv_bfloat162 p2 = __floats2bfloat162_rn(o4, o5);
                __nv_bfloat162 p3 = __floats2bfloat162_rn(o6, o7);
                uint4 w = make_uint4(*(uint32_t*)&p0, *(uint32_t*)&p1,
                                     *(uint32_t*)&p2, *(uint32_t*)&p3);
                *(uint4*)&((bf16*)Cout)[gr * Nfull + gc0] = w;
            }
            __syncwarp();
        }
    }
}

// ---------------- fused cross-attention (wmma), QKV stride 3072 ----------------
#define SMEM_ATT 197632

__global__ void __launch_bounds__(256) attn_kernel() {
    extern __shared__ char smraw[];
    bf16*  Ks = (bf16*)smraw;
    bf16*  Vs = Ks + 256 * 136;
    bf16*  Qs = Vs + 256 * 136;
    float* Ss = (float*)(Qs + 32 * 136);
    bf16*  Ps = (bf16*)(Ss + 32 * 256);
    float* Os = Ss;

    int tid = threadIdx.x, wid = tid >> 5, lane = tid & 31;
    int bx = blockIdx.x;
    int s  = bx >> 9;
    int bh = bx & 511;
    int b = bh >> 3, h = bh & 7;

    const bf16* qs_op = g_qkv + (long)(1 - s) * TOK * QKVN;
    const bf16* qs_s  = g_qkv + (long)s * TOK * QKVN;
    const bf16* Qg = qs_op + ((long)b * NSEQ) * QKVN + 0 * DMODEL + h * DKH;
    const bf16* Kg = qs_s  + ((long)b * NSEQ) * QKVN + 1 * DMODEL + h * DKH;
    const bf16* Vg = qs_s  + ((long)b * NSEQ) * QKVN + 2 * DMODEL + h * DKH;
    bf16*       Og = g_attn + (long)s * TOK * DMODEL + ((long)b * NSEQ) * DMODEL + h * DKH;

#pragma unroll
    for (int i = 0; i < 16; i++) {
        int v = tid + i * 256;
        int r = v >> 4, c8 = (v & 15) * 8;
        *(uint4*)&Ks[r * 136 + c8] = *(const uint4*)&Kg[(long)r * QKVN + c8];
        *(uint4*)&Vs[r * 136 + c8] = *(const uint4*)&Vg[(long)r * QKVN + c8];
    }
    __syncthreads();

    const float scale = 0.08838834764831845f;

    for (int qc = 0; qc < 8; qc++) {
#pragma unroll
        for (int i = 0; i < 2; i++) {
            int v = tid + i * 256;
            int r = v >> 4, c8 = (v & 15) * 8;
            *(uint4*)&Qs[r * 136 + c8] = *(const uint4*)&Qg[(long)(qc * 32 + r) * QKVN + c8];
        }
        __syncthreads();

        {
            wmma::fragment<wmma::accumulator, 16, 16, 16, float> c[2][2];
#pragma unroll
            for (int i = 0; i < 2; i++)
#pragma unroll
                for (int j = 0; j < 2; j++) wmma::fill_fragment(c[i][j], 0.f);
#pragma unroll
            for (int kt = 0; kt < 8; kt++) {
                wmma::fragment<wmma::matrix_a, 16, 16, 16, bf16, wmma::row_major> a[2];
                wmma::fragment<wmma::matrix_b, 16, 16, 16, bf16, wmma::col_major> bb[2];
#pragma unroll
                for (int i = 0; i < 2; i++)
                    wmma::load_matrix_sync(a[i], &Qs[(i * 16) * 136 + kt * 16], 136);
#pragma unroll
                for (int j = 0; j < 2; j++)
                    wmma::load_matrix_sync(bb[j], &Ks[(wid * 32 + j * 16) * 136 + kt * 16], 136);
#pragma unroll
                for (int i = 0; i < 2; i++)
#pragma unroll
                    for (int j = 0; j < 2; j++)
                        wmma::mma_sync(c[i][j], a[i], bb[j], c[i][j]);
            }
#pragma unroll
            for (int i = 0; i < 2; i++)
#pragma unroll
                for (int j = 0; j < 2; j++) {
#pragma unroll
                    for (int t = 0; t < c[i][j].num_elements; t++) c[i][j].x[t] *= scale;
                    wmma::store_matrix_sync(&Ss[(i * 16) * 256 + wid * 32 + j * 16],
                                            c[i][j], 256, wmma::mem_row_major);
                }
        }
        __syncthreads();

        {
#pragma unroll
            for (int rq = 0; rq < 4; rq++) {
                int row = wid * 4 + rq;
                float* srow = Ss + row * 256;
                float vals[8];
                float mx = -1e30f;
#pragma unroll
                for (int i = 0; i < 8; i++) { vals[i] = srow[lane + i * 32]; mx = fmaxf(mx, vals[i]); }
#pragma unroll
                for (int o = 16; o > 0; o >>= 1) mx = fmaxf(mx, __shfl_xor_sync(0xffffffffu, mx, o));
                float sum = 0.f;
#pragma unroll
                for (int i = 0; i < 8; i++) { vals[i] = __expf(vals[i] - mx); sum += vals[i]; }
#pragma unroll
                for (int o = 16; o > 0; o >>= 1) sum += __shfl_xor_sync(0xffffffffu, sum, o);
                float inv = 1.f / sum;
#pragma unroll
                for (int i = 0; i < 8; i++)
                    Ps[row * 264 + lane + i * 32] = __float2bfloat16(vals[i] * inv);
            }
        }
        __syncthreads();

        {
            wmma::fragment<wmma::accumulator, 16, 16, 16, float> c2[2];
#pragma unroll
            for (int i = 0; i < 2; i++) wmma::fill_fragment(c2[i], 0.f);
#pragma unroll
            for (int kt = 0; kt < 16; kt++) {
                wmma::fragment<wmma::matrix_a, 16, 16, 16, bf16, wmma::row_major> a[2];
                wmma::fragment<wmma::matrix_b, 16, 16, 16, bf16, wmma::row_major> bb;
#pragma unroll
                for (int i = 0; i < 2; i++)
                    wmma::load_matrix_sync(a[i], &Ps[(i * 16) * 264 + kt * 16], 264);
                wmma::load_matrix_sync(bb, &Vs[(kt * 16) * 136 + wid * 16], 136);
#pragma unroll
                for (int i = 0; i < 2; i++) wmma::mma_sync(c2[i], a[i], bb, c2[i]);
            }
#pragma unroll
            for (int i = 0; i < 2; i++)
                wmma::store_matrix_sync(&Os[(i * 16) * 128 + wid * 16], c2[i], 128, wmma::mem_row_major);
        }
        __syncthreads();

#pragma unroll
        for (int i = 0; i < 16; i++) {
            int e = tid + i * 256;
            int r = e >> 7, cc = e & 127;
            Og[(long)(qc * 32 + r) * DMODEL + cc] = __float2bfloat16(Os[r * 128 + cc]);
        }
        __syncthreads();
    }
}

// ---------------- host ----------------
extern "C" void kernel_launch(void* const* d_in, const int* in_sizes, int n_in,
                              void* d_out, int out_size) {
    const float* rgb   = (const float*)d_in[0];
    const float* ir    = (const float*)d_in[1];
    const float* ln1g  = (const float*)d_in[2];
    const float* ln1b  = (const float*)d_in[3];
    const float* ln2g  = (const float*)d_in[4];
    const float* ln2b  = (const float*)d_in[5];
    const float* Wqv   = (const float*)d_in[6];
    const float* bqv   = (const float*)d_in[7];
    const float* Wqi   = (const float*)d_in[8];
    const float* bqi   = (const float*)d_in[9];
    const float* Wov   = (const float*)d_in[10];
    const float* bov   = (const float*)d_in[11];
    const float* Woi   = (const float*)d_in[12];
    const float* boi   = (const float*)d_in[13];
    const float* blkg  = (const float*)d_in[14];
    const float* blkb  = (const float*)d_in[15];
    const float* W1v   = (const float*)d_in[16];
    const float* b1v   = (const float*)d_in[17];
    const float* W2v   = (const float*)d_in[18];
    const float* b2v   = (const float*)d_in[19];
    const float* W1i   = (const float*)d_in[20];
    const float* b1i   = (const float*)d_in[21];
    const float* W2i   = (const float*)d_in[22];
    const float* b2i   = (const float*)d_in[23];
    const float* coeffs = (const float*)d_in[24];

    bf16 *xn, *qkv, *attn, *h1, *wqkv, *wo, *w1, *w2;
    float* attres;
    cudaGetSymbolAddress((void**)&xn, g_xn);
    cudaGetSymbolAddress((void**)&qkv, g_qkv);
    cudaGetSymbolAddress((void**)&attn, g_attn);
    cudaGetSymbolAddress((void**)&attres, g_attres);
    cudaGetSymbolAddress((void**)&h1, g_h1);
    cudaGetSymbolAddress((void**)&wqkv, g_wqkv);
    cudaGetSymbolAddress((void**)&wo, g_wo);
    cudaGetSymbolAddress((void**)&w1, g_w1);
    cudaGetSymbolAddress((void**)&w2, g_w2);

    const long DD = (long)DMODEL * DMODEL;
    const long TD = (long)TOK * DMODEL;
    const long QD = (long)TOK * QKVN;

    // transpose-convert weights to [N, K] bf16
    for (int t = 0; t < 3; t++) {
        cvtT_kernel<<<dim3(DMODEL/32, DMODEL/32), 256>>>(Wqv + t * DD, wqkv + t * DD, DMODEL, DMODEL);
        cvtT_kernel<<<dim3(DMODEL/32, DMODEL/32), 256>>>(Wqi + t * DD, wqkv + 3 * DD + t * DD, DMODEL, DMODEL);
    }
    cvtT_kernel<<<dim3(DMODEL/32, DMODEL/32), 256>>>(Wov, wo, DMODEL, DMODEL);
    cvtT_kernel<<<dim3(DMODEL/32, DMODEL/32), 256>>>(Woi, wo + DD, DMODEL, DMODEL);
    cvtT_kernel<<<dim3(HID/32, DMODEL/32), 256>>>(W1v, w1, DMODEL, HID);
    cvtT_kernel<<<dim3(HID/32, DMODEL/32), 256>>>(W1i, w1 + (long)HID * DMODEL, DMODEL, HID);
    cvtT_kernel<<<dim3(DMODEL/32, HID/32), 256>>>(W2v, w2, HID, DMODEL);
    cvtT_kernel<<<dim3(DMODEL/32, HID/32), 256>>>(W2i, w2 + (long)DMODEL * HID, HID, DMODEL);

    // LN per stream
    ln_kernel<<<TOK / 8, 256>>>(rgb, ln1g, ln1b, xn);
    ln_kernel<<<TOK / 8, 256>>>(ir, ln2g, ln2b, xn + TD);

    cudaFuncSetAttribute(tgemm_kernel<0>, cudaFuncAttributeMaxDynamicSharedMemorySize, GSMEM);
    cudaFuncSetAttribute(tgemm_kernel<1>, cudaFuncAttributeMaxDynamicSharedMemorySize, GSMEM);
    cudaFuncSetAttribute(tgemm_kernel<2>, cudaFuncAttributeMaxDynamicSharedMemorySize, GSMEM);

    // fused QKV: [16384,1024] @ [3072,1024]^T
    for (int s = 0; s < 2; s++) {
        tgemm_kernel<0><<<dim3(QKVN/128, TOK/128), 128, GSMEM>>>(
            xn + s * TD, wqkv + (long)s * 3 * DD, s ? bqi : bqv,
            nullptr, nullptr, 0, 0, qkv + s * QD, QKVN, DMODEL);
    }

    // fused cross attention
    cudaFuncSetAttribute(attn_kernel, cudaFuncAttributeMaxDynamicSharedMemorySize, SMEM_ATT);
    attn_kernel<<<1024, 256, SMEM_ATT>>>();

    // output projection + coeff residual -> fp32 attres
    for (int s = 0; s < 2; s++) {
        tgemm_kernel<2><<<dim3(DMODEL/128, TOK/128), 128, GSMEM>>>(
            attn + s * TD, wo + s * DD, s ? boi : bov,
            s ? ir : rgb, coeffs, 2 * s, 2 * s + 1,
            attres + s * TD, DMODEL, DMODEL);
    }

    // block LN (shared params)
    ln_kernel<<<TOK / 8, 256>>>(attres, blkg, blkb, xn);
    ln_kernel<<<TOK / 8, 256>>>(attres + TD, blkg, blkb, xn + TD);

    // MLP1 (gelu)
    for (int s = 0; s < 2; s++) {
        tgemm_kernel<1><<<dim3(HID/128, TOK/128), 128, GSMEM>>>(
            xn + s * TD, w1 + (long)s * HID * DMODEL, s ? b1i : b1v,
            nullptr, nullptr, 0, 0, h1 + (long)s * TOK * HID, HID, DMODEL);
    }

    // MLP2 + coeff residual -> d_out (fp32)
    for (int s = 0; s < 2; s++) {
        tgemm_kernel<2><<<dim3(DMODEL/128, TOK/128), 128, GSMEM>>>(
            h1 + (long)s * TOK * HID, w2 + (long)s * DMODEL * HID, s ? b2i : b2v,
            attres + s * TD, coeffs, 4 + 2 * s, 5 + 2 * s,
            (float*)d_out + s * TD, DMODEL, HID);
    }
}

// round 11
// speedup vs baseline: 2.1367x; 1.0335x over previous
#include <cuda_runtime.h>
#include <cuda_bf16.h>
#include <mma.h>
#include <math.h>
#include <stdint.h>

using namespace nvcuda;
typedef __nv_bfloat16 bf16;

#define TOK     16384
#define DMODEL  1024
#define HID     4096
#define NSEQ    256
#define DKH     128
#define QKVN    3072

// ---------------- scratch ----------------
__device__ bf16  g_xn    [2L*TOK*DMODEL];
__device__ bf16  g_qkv   [2L*TOK*QKVN];      // [stream][tok][3072] (Q|K|V)
__device__ bf16  g_attn  [2L*TOK*DMODEL];
__device__ float g_attres[2L*TOK*DMODEL];
__device__ bf16  g_h1    [2L*TOK*HID];
__device__ bf16  g_wqkv  [2L*QKVN*DMODEL];   // transposed [N,K]
__device__ bf16  g_wo    [2L*DMODEL*DMODEL];
__device__ bf16  g_w1    [2L*HID*DMODEL];
__device__ bf16  g_w2    [2L*DMODEL*HID];

// ---------------- helpers ----------------
__device__ __forceinline__ void cp_async16(void* d, const void* s) {
    unsigned ds = (unsigned)__cvta_generic_to_shared(d);
    asm volatile("cp.async.cg.shared.global [%0], [%1], 16;\n" :: "r"(ds), "l"(s));
}
__device__ __forceinline__ void cp_commit() { asm volatile("cp.async.commit_group;\n"); }

// ---------------- transpose + fp32->bf16 convert: src[K,N] -> dst[N,K], z slices ----------------
__global__ void cvtT_kernel(const float* __restrict__ src, bf16* __restrict__ dst, int K, int N) {
    __shared__ float t[32][33];
    long zo = (long)blockIdx.z * (long)K * N;
    int n0 = blockIdx.x * 32, k0 = blockIdx.y * 32;
    int tx = threadIdx.x & 31, ty = threadIdx.x >> 5;
#pragma unroll
    for (int i = 0; i < 32; i += 8)
        t[ty + i][tx] = src[zo + (long)(k0 + ty + i) * N + n0 + tx];
    __syncthreads();
#pragma unroll
    for (int i = 0; i < 32; i += 8)
        dst[zo + (long)(n0 + ty + i) * K + k0 + tx] = __float2bfloat16(t[tx][ty + i]);
}

// ---------------- LayerNorm (fp32 in -> bf16 out) ----------------
__global__ void ln_kernel(const float* __restrict__ x, const float* __restrict__ gamma,
                          const float* __restrict__ beta, bf16* __restrict__ out) {
    int warp = threadIdx.x >> 5, lane = threadIdx.x & 31;
    long row = (long)blockIdx.x * 8 + warp;
    const float* xr = x + row * DMODEL;
    float4 v[8];
    float s = 0.f, s2 = 0.f;
#pragma unroll
    for (int i = 0; i < 8; i++) {
        v[i] = *reinterpret_cast<const float4*>(xr + i * 128 + lane * 4);
        s  += v[i].x + v[i].y + v[i].z + v[i].w;
        s2 += v[i].x*v[i].x + v[i].y*v[i].y + v[i].z*v[i].z + v[i].w*v[i].w;
    }
#pragma unroll
    for (int o = 16; o > 0; o >>= 1) {
        s  += __shfl_xor_sync(0xffffffffu, s,  o);
        s2 += __shfl_xor_sync(0xffffffffu, s2, o);
    }
    float m  = s * (1.f / 1024.f);
    float var = s2 * (1.f / 1024.f) - m * m;
    float rs = rsqrtf(var + 1e-5f);
    bf16* orow = out + row * DMODEL;
#pragma unroll
    for (int i = 0; i < 8; i++) {
        int c = i * 128 + lane * 4;
        float4 g4 = *reinterpret_cast<const float4*>(gamma + c);
        float4 b4 = *reinterpret_cast<const float4*>(beta + c);
        float o0 = (v[i].x - m) * rs * g4.x + b4.x;
        float o1 = (v[i].y - m) * rs * g4.y + b4.y;
        float o2 = (v[i].z - m) * rs * g4.z + b4.z;
        float o3 = (v[i].w - m) * rs * g4.w + b4.w;
        __nv_bfloat162 p0 = __floats2bfloat162_rn(o0, o1);
        __nv_bfloat162 p1 = __floats2bfloat162_rn(o2, o3);
        uint2 p;
        p.x = *reinterpret_cast<unsigned*>(&p0);
        p.y = *reinterpret_cast<unsigned*>(&p1);
        *reinterpret_cast<uint2*>(orow + c) = p;
    }
}

// ---------------- wmma GEMM: C[M,Nfull] = A[M,K] @ Bt[N,K]^T + epilogue ----------------
// CTA 128x128, 4 warps of 64x64, BK=64, 3-stage cp.async, ONE barrier per iter, occ 2.
#define PIPE   3
#define LDT    72
#define ASTGB  (128 * LDT * 2)        // 18432 B
#define STGB   (2 * ASTGB)            // 36864 B per stage (A+B)
#define EOFF   (PIPE * STGB)          // 110592
#define GSMEM  (EOFF + 4 * 1024)      // 114688

template <int EPI>
__global__ void __launch_bounds__(128, 2) tgemm_kernel(
    const bf16* __restrict__ A, const bf16* __restrict__ Bt,
    const float* __restrict__ bias, const float* __restrict__ res,
    const float* __restrict__ coeffs, int ci_res, int ci_out,
    void* __restrict__ Cout, int Nfull, int K)
{
    extern __shared__ char sm[];
    int tid = threadIdx.x, wid = tid >> 5, lane = tid & 31;
    int warpM = wid & 1, warpN = wid >> 1;
    long bm = (long)blockIdx.y * 128;
    long bn = (long)blockIdx.x * 128;
    int KT = K >> 6;

    wmma::fragment<wmma::accumulator, 16, 16, 16, float> acc[4][4];
#pragma unroll
    for (int i = 0; i < 4; i++)
#pragma unroll
        for (int j = 0; j < 4; j++) wmma::fill_fragment(acc[i][j], 0.f);

    // loader mapping: 1024 chunks of 16B per operand per stage, 128 threads -> 8 each
#pragma unroll
    for (int s = 0; s < PIPE - 1; s++) {
        char* stg = sm + s * STGB;
        long koff = (long)s * 64;
#pragma unroll
        for (int i = 0; i < 8; i++) {
            int id = tid + i * 128;
            int r = id >> 3, c8 = (id & 7) * 8;
            cp_async16(stg + (r * LDT + c8) * 2, A + (bm + r) * K + koff + c8);
            cp_async16(stg + ASTGB + (r * LDT + c8) * 2, Bt + (bn + r) * K + koff + c8);
        }
        cp_commit();
    }

    for (int kt = 0; kt < KT; kt++) {
        asm volatile("cp.async.wait_group 1;\n");
        __syncthreads();

        // prefetch stage kt+2 (its buffer was last read in iter kt-1; barrier passed)
        int pf = kt + PIPE - 1;
        if (pf < KT) {
            char* stg = sm + (pf % PIPE) * STGB;
            long koff = (long)pf * 64;
#pragma unroll
            for (int i = 0; i < 8; i++) {
                int id = tid + i * 128;
                int r = id >> 3, c8 = (id & 7) * 8;
                cp_async16(stg + (r * LDT + c8) * 2, A + (bm + r) * K + koff + c8);
                cp_async16(stg + ASTGB + (r * LDT + c8) * 2, Bt + (bn + r) * K + koff + c8);
            }
        }
        cp_commit();

        bf16* As = (bf16*)(sm + (kt % PIPE) * STGB);
        bf16* Bs = (bf16*)(sm + (kt % PIPE) * STGB + ASTGB);
#pragma unroll
        for (int ks = 0; ks < 4; ks++) {
            wmma::fragment<wmma::matrix_a, 16, 16, 16, bf16, wmma::row_major> a[4];
            wmma::fragment<wmma::matrix_b, 16, 16, 16, bf16, wmma::col_major> b[4];
#pragma unroll
            for (int i = 0; i < 4; i++)
                wmma::load_matrix_sync(a[i], &As[(warpM * 64 + i * 16) * LDT + ks * 16], LDT);
#pragma unroll
            for (int j = 0; j < 4; j++)
                wmma::load_matrix_sync(b[j], &Bs[(warpN * 64 + j * 16) * LDT + ks * 16], LDT);
#pragma unroll
            for (int i = 0; i < 4; i++)
#pragma unroll
                for (int j = 0; j < 4; j++)
                    wmma::mma_sync(acc[i][j], a[i], b[j], acc[i][j]);
        }
    }

    // ---- epilogue (per-warp private smem staging, vectorized stores) ----
    float* ebuf = (float*)(sm + EOFF + wid * 1024);
    float cr = 0.f, co = 0.f;
    if (EPI == 2) { cr = coeffs[ci_res]; co = coeffs[ci_out]; }
    int rr = lane >> 1, half = lane & 1;
#pragma unroll
    for (int i = 0; i < 4; i++) {
#pragma unroll
        for (int j = 0; j < 4; j++) {
            wmma::store_matrix_sync(ebuf, acc[i][j], 16, wmma::mem_row_major);
            __syncwarp();
            long gr  = bm + warpM * 64 + i * 16 + rr;
            long gc0 = bn + warpN * 64 + j * 16 + half * 8;
            float4 v0 = *(float4*)&ebuf[rr * 16 + half * 8];
            float4 v1 = *(float4*)&ebuf[rr * 16 + half * 8 + 4];
            float4 b0 = *(const float4*)&bias[gc0];
            float4 b1 = *(const float4*)&bias[gc0 + 4];
            float o0 = v0.x + b0.x, o1 = v0.y + b0.y, o2 = v0.z + b0.z, o3 = v0.w + b0.w;
            float o4 = v1.x + b1.x, o5 = v1.y + b1.y, o6 = v1.z + b1.z, o7 = v1.w + b1.w;
            if (EPI == 1) {
                o0 = 0.5f*o0*(1.f+erff(o0*0.70710678f)); o1 = 0.5f*o1*(1.f+erff(o1*0.70710678f));
                o2 = 0.5f*o2*(1.f+erff(o2*0.70710678f)); o3 = 0.5f*o3*(1.f+erff(o3*0.70710678f));
                o4 = 0.5f*o4*(1.f+erff(o4*0.70710678f)); o5 = 0.5f*o5*(1.f+erff(o5*0.70710678f));
                o6 = 0.5f*o6*(1.f+erff(o6*0.70710678f)); o7 = 0.5f*o7*(1.f+erff(o7*0.70710678f));
            }
            if (EPI == 2) {
                float4 r0 = *(const float4*)&res[gr * Nfull + gc0];
                float4 r1 = *(const float4*)&res[gr * Nfull + gc0 + 4];
                float4 w0 = make_float4(cr*r0.x + co*o0, cr*r0.y + co*o1,
                                        cr*r0.z + co*o2, cr*r0.w + co*o3);
                float4 w1 = make_float4(cr*r1.x + co*o4, cr*r1.y + co*o5,
                                        cr*r1.z + co*o6, cr*r1.w + co*o7);
                *(float4*)&((float*)Cout)[gr * Nfull + gc0]     = w0;
                *(float4*)&((float*)Cout)[gr * Nfull + gc0 + 4] = w1;
            } else {
                __nv_bfloat162 p0 = __floats2bfloat162_rn(o0, o1);
                __nv_bfloat162 p1 = __floats2bfloat162_rn(o2, o3);
                __nv_bfloat162 p2 = __floats2bfloat162_rn(o4, o5);
                __nv_bfloat162 p3 = __floats2bfloat162_rn(o6, o7);
                uint4 w = make_uint4(*(uint32_t*)&p0, *(uint32_t*)&p1,
                                     *(uint32_t*)&p2, *(uint32_t*)&p3);
                *(uint4*)&((bf16*)Cout)[gr * Nfull + gc0] = w;
            }
            __syncwarp();
        }
    }
}

// ---------------- fused cross-attention (wmma), QKV stride 3072 ----------------
#define SMEM_ATT 197632

__global__ void __launch_bounds__(256) attn_kernel() {
    extern __shared__ char smraw[];
    bf16*  Ks = (bf16*)smraw;
    bf16*  Vs = Ks + 256 * 136;
    bf16*  Qs = Vs + 256 * 136;
    float* Ss = (float*)(Qs + 32 * 136);
    bf16*  Ps = (bf16*)(Ss + 32 * 256);
    float* Os = Ss;

    int tid = threadIdx.x, wid = tid >> 5, lane = tid & 31;
    int bx = blockIdx.x;
    int s  = bx >> 9;
    int bh = bx & 511;
    int b = bh >> 3, h = bh & 7;

    const bf16* qs_op = g_qkv + (long)(1 - s) * TOK * QKVN;
    const bf16* qs_s  = g_qkv + (long)s * TOK * QKVN;
    const bf16* Qg = qs_op + ((long)b * NSEQ) * QKVN + 0 * DMODEL + h * DKH;
    const bf16* Kg = qs_s  + ((long)b * NSEQ) * QKVN + 1 * DMODEL + h * DKH;
    const bf16* Vg = qs_s  + ((long)b * NSEQ) * QKVN + 2 * DMODEL + h * DKH;
    bf16*       Og = g_attn + (long)s * TOK * DMODEL + ((long)b * NSEQ) * DMODEL + h * DKH;

#pragma unroll
    for (int i = 0; i < 16; i++) {
        int v = tid + i * 256;
        int r = v >> 4, c8 = (v & 15) * 8;
        *(uint4*)&Ks[r * 136 + c8] = *(const uint4*)&Kg[(long)r * QKVN + c8];
        *(uint4*)&Vs[r * 136 + c8] = *(const uint4*)&Vg[(long)r * QKVN + c8];
    }
    __syncthreads();

    const float scale = 0.08838834764831845f;

    for (int qc = 0; qc < 8; qc++) {
#pragma unroll
        for (int i = 0; i < 2; i++) {
            int v = tid + i * 256;
            int r = v >> 4, c8 = (v & 15) * 8;
            *(uint4*)&Qs[r * 136 + c8] = *(const uint4*)&Qg[(long)(qc * 32 + r) * QKVN + c8];
        }
        __syncthreads();

        {
            wmma::fragment<wmma::accumulator, 16, 16, 16, float> c[2][2];
#pragma unroll
            for (int i = 0; i < 2; i++)
#pragma unroll
                for (int j = 0; j < 2; j++) wmma::fill_fragment(c[i][j], 0.f);
#pragma unroll
            for (int kt = 0; kt < 8; kt++) {
                wmma::fragment<wmma::matrix_a, 16, 16, 16, bf16, wmma::row_major> a[2];
                wmma::fragment<wmma::matrix_b, 16, 16, 16, bf16, wmma::col_major> bb[2];
#pragma unroll
                for (int i = 0; i < 2; i++)
                    wmma::load_matrix_sync(a[i], &Qs[(i * 16) * 136 + kt * 16], 136);
#pragma unroll
                for (int j = 0; j < 2; j++)
                    wmma::load_matrix_sync(bb[j], &Ks[(wid * 32 + j * 16) * 136 + kt * 16], 136);
#pragma unroll
                for (int i = 0; i < 2; i++)
#pragma unroll
                    for (int j = 0; j < 2; j++)
                        wmma::mma_sync(c[i][j], a[i], bb[j], c[i][j]);
            }
#pragma unroll
            for (int i = 0; i < 2; i++)
#pragma unroll
                for (int j = 0; j < 2; j++) {
#pragma unroll
                    for (int t = 0; t < c[i][j].num_elements; t++) c[i][j].x[t] *= scale;
                    wmma::store_matrix_sync(&Ss[(i * 16) * 256 + wid * 32 + j * 16],
                                            c[i][j], 256, wmma::mem_row_major);
                }
        }
        __syncthreads();

        {
#pragma unroll
            for (int rq = 0; rq < 4; rq++) {
                int row = wid * 4 + rq;
                float* srow = Ss + row * 256;
                float vals[8];
                float mx = -1e30f;
#pragma unroll
                for (int i = 0; i < 8; i++) { vals[i] = srow[lane + i * 32]; mx = fmaxf(mx, vals[i]); }
#pragma unroll
                for (int o = 16; o > 0; o >>= 1) mx = fmaxf(mx, __shfl_xor_sync(0xffffffffu, mx, o));
                float sum = 0.f;
#pragma unroll
                for (int i = 0; i < 8; i++) { vals[i] = __expf(vals[i] - mx); sum += vals[i]; }
#pragma unroll
                for (int o = 16; o > 0; o >>= 1) sum += __shfl_xor_sync(0xffffffffu, sum, o);
                float inv = 1.f / sum;
#pragma unroll
                for (int i = 0; i < 8; i++)
                    Ps[row * 264 + lane + i * 32] = __float2bfloat16(vals[i] * inv);
            }
        }
        __syncthreads();

        {
            wmma::fragment<wmma::accumulator, 16, 16, 16, float> c2[2];
#pragma unroll
            for (int i = 0; i < 2; i++) wmma::fill_fragment(c2[i], 0.f);
#pragma unroll
            for (int kt = 0; kt < 16; kt++) {
                wmma::fragment<wmma::matrix_a, 16, 16, 16, bf16, wmma::row_major> a[2];
                wmma::fragment<wmma::matrix_b, 16, 16, 16, bf16, wmma::row_major> bb;
#pragma unroll
                for (int i = 0; i < 2; i++)
                    wmma::load_matrix_sync(a[i], &Ps[(i * 16) * 264 + kt * 16], 264);
                wmma::load_matrix_sync(bb, &Vs[(kt * 16) * 136 + wid * 16], 136);
#pragma unroll
                for (int i = 0; i < 2; i++) wmma::mma_sync(c2[i], a[i], bb, c2[i]);
            }
#pragma unroll
            for (int i = 0; i < 2; i++)
                wmma::store_matrix_sync(&Os[(i * 16) * 128 + wid * 16], c2[i], 128, wmma::mem_row_major);
        }
        __syncthreads();

#pragma unroll
        for (int i = 0; i < 16; i++) {
            int e = tid + i * 256;
            int r = e >> 7, cc = e & 127;
            Og[(long)(qc * 32 + r) * DMODEL + cc] = __float2bfloat16(Os[r * 128 + cc]);
        }
        __syncthreads();
    }
}

// ---------------- host ----------------
extern "C" void kernel_launch(void* const* d_in, const int* in_sizes, int n_in,
                              void* d_out, int out_size) {
    const float* rgb   = (const float*)d_in[0];
    const float* ir    = (const float*)d_in[1];
    const float* ln1g  = (const float*)d_in[2];
    const float* ln1b  = (const float*)d_in[3];
    const float* ln2g  = (const float*)d_in[4];
    const float* ln2b  = (const float*)d_in[5];
    const float* Wqv   = (const float*)d_in[6];
    const float* bqv   = (const float*)d_in[7];
    const float* Wqi   = (const float*)d_in[8];
    const float* bqi   = (const float*)d_in[9];
    const float* Wov   = (const float*)d_in[10];
    const float* bov   = (const float*)d_in[11];
    const float* Woi   = (const float*)d_in[12];
    const float* boi   = (const float*)d_in[13];
    const float* blkg  = (const float*)d_in[14];
    const float* blkb  = (const float*)d_in[15];
    const float* W1v   = (const float*)d_in[16];
    const float* b1v   = (const float*)d_in[17];
    const float* W2v   = (const float*)d_in[18];
    const float* b2v   = (const float*)d_in[19];
    const float* W1i   = (const float*)d_in[20];
    const float* b1i   = (const float*)d_in[21];
    const float* W2i   = (const float*)d_in[22];
    const float* b2i   = (const float*)d_in[23];
    const float* coeffs = (const float*)d_in[24];

    bf16 *xn, *qkv, *attn, *h1, *wqkv, *wo, *w1, *w2;
    float* attres;
    cudaGetSymbolAddress((void**)&xn, g_xn);
    cudaGetSymbolAddress((void**)&qkv, g_qkv);
    cudaGetSymbolAddress((void**)&attn, g_attn);
    cudaGetSymbolAddress((void**)&attres, g_attres);
    cudaGetSymbolAddress((void**)&h1, g_h1);
    cudaGetSymbolAddress((void**)&wqkv, g_wqkv);
    cudaGetSymbolAddress((void**)&wo, g_wo);
    cudaGetSymbolAddress((void**)&w1, g_w1);
    cudaGetSymbolAddress((void**)&w2, g_w2);

    const long DD = (long)DMODEL * DMODEL;
    const long TD = (long)TOK * DMODEL;
    const long QD = (long)TOK * QKVN;

    cudaFuncSetAttribute(tgemm_kernel<0>, cudaFuncAttributeMaxDynamicSharedMemorySize, GSMEM);
    cudaFuncSetAttribute(tgemm_kernel<1>, cudaFuncAttributeMaxDynamicSharedMemorySize, GSMEM);
    cudaFuncSetAttribute(tgemm_kernel<2>, cudaFuncAttributeMaxDynamicSharedMemorySize, GSMEM);
    cudaFuncSetAttribute(attn_kernel, cudaFuncAttributeMaxDynamicSharedMemorySize, SMEM_ATT);

    // #0,#1: LN per stream
    ln_kernel<<<TOK / 8, 256>>>(rgb, ln1g, ln1b, xn);
    ln_kernel<<<TOK / 8, 256>>>(ir, ln2g, ln2b, xn + TD);

    // #2,#3: QKV weight transpose-converts (3 slices each via gridDim.z)
    cvtT_kernel<<<dim3(DMODEL/32, DMODEL/32, 3), 256>>>(Wqv, wqkv, DMODEL, DMODEL);
    cvtT_kernel<<<dim3(DMODEL/32, DMODEL/32, 3), 256>>>(Wqi, wqkv + 3 * DD, DMODEL, DMODEL);

    // #4,#5: fused QKV GEMMs  (#5 is what ncu -s 5 captures)
    for (int s = 0; s < 2; s++) {
        tgemm_kernel<0><<<dim3(QKVN/128, TOK/128), 128, GSMEM>>>(
            xn + s * TD, wqkv + (long)s * 3 * DD, s ? bqi : bqv,
            nullptr, nullptr, 0, 0, qkv + s * QD, QKVN, DMODEL);
    }

    // remaining weight converts (needed later)
    cvtT_kernel<<<dim3(DMODEL/32, DMODEL/32, 1), 256>>>(Wov, wo, DMODEL, DMODEL);
    cvtT_kernel<<<dim3(DMODEL/32, DMODEL/32, 1), 256>>>(Woi, wo + DD, DMODEL, DMODEL);
    cvtT_kernel<<<dim3(HID/32, DMODEL/32, 1), 256>>>(W1v, w1, DMODEL, HID);
    cvtT_kernel<<<dim3(HID/32, DMODEL/32, 1), 256>>>(W1i, w1 + (long)HID * DMODEL, DMODEL, HID);
    cvtT_kernel<<<dim3(DMODEL/32, HID/32, 1), 256>>>(W2v, w2, HID, DMODEL);
    cvtT_kernel<<<dim3(DMODEL/32, HID/32, 1), 256>>>(W2i, w2 + (long)DMODEL * HID, HID, DMODEL);

    // fused cross attention
    attn_kernel<<<1024, 256, SMEM_ATT>>>();

    // output projection + coeff residual -> fp32 attres
    for (int s = 0; s < 2; s++) {
        tgemm_kernel<2><<<dim3(DMODEL/128, TOK/128), 128, GSMEM>>>(
            attn + s * TD, wo + s * DD, s ? boi : bov,
            s ? ir : rgb, coeffs, 2 * s, 2 * s + 1,
            attres + s * TD, DMODEL, DMODEL);
    }

    // block LN (shared params)
    ln_kernel<<<TOK / 8, 256>>>(attres, blkg, blkb, xn);
    ln_kernel<<<TOK / 8, 256>>>(attres + TD, blkg, blkb, xn + TD);

    // MLP1 (gelu)
    for (int s = 0; s < 2; s++) {
        tgemm_kernel<1><<<dim3(HID/128, TOK/128), 128, GSMEM>>>(
            xn + s * TD, w1 + (long)s * HID * DMODEL, s ? b1i : b1v,
            nullptr, nullptr, 0, 0, h1 + (long)s * TOK * HID, HID, DMODEL);
    }

    // MLP2 + coeff residual -> d_out (fp32)
    for (int s = 0; s < 2; s++) {
        tgemm_kernel<2><<<dim3(DMODEL/128, TOK/128), 128, GSMEM>>>(
            h1 + (long)s * TOK * HID, w2 + (long)s * DMODEL * HID, s ? b2i : b2v,
            attres + s * TD, coeffs, 4 + 2 * s, 5 + 2 * s,
            (float*)d_out + s * TD, DMODEL, HID);
    }
}